// round 13
// baseline (speedup 1.0000x reference)
#include <cuda_runtime.h>
#include <cstdint>

// MonarchOutProjection:
//   h2[t][b][n]    = sum_m L[b][n][m] * x[t][m*32+b]
//   out[t][i*32+j] = sum_m R[j][i][m] * h2[t][m][j]
//
// R12: R=4 (4 n-rows x 2 t per thread) with pair-packed weights + diagonal
// FFMA2 -> crossbar cost/tile quartered vs R9. Stage1 fill via prefetched
// LDG.128 + swizzled STS.32 (no scalar cp.async). 256-thr CTAs, 2/SM,
// CTA owns an eighth (4 blocks); warp = (block, n-half).

#define TILE_T 16
#define BROW 516                        // per-block smem row: 32m*16t + 4
#define XS_FLOATS (4 * BROW)            // 2064 per buffer (4 blocks)
#define OS_FLOATS (32 * 72)             // 2304: os[i][jl][t] = i*72 + jl*18 + t
#define SMEM1_BYTES (2 * XS_FLOATS * 4)                 // 16512
#define SMEM2_BYTES ((2 * XS_FLOATS + OS_FLOATS) * 4)   // 25728

// g_h2[tile][b][n][t] : idx = tile*16384 + b*512 + n*16 + t
__device__ float g_h2[33554432];

__device__ __forceinline__ unsigned smem_addr(const void* p) {
    return (unsigned)__cvta_generic_to_shared(p);
}
__device__ __forceinline__ void cp_async16(unsigned dst, const float* src) {
    asm volatile("cp.async.cg.shared.global [%0], [%1], 16;" :: "r"(dst), "l"(src));
}
__device__ __forceinline__ void cp_commit() {
    asm volatile("cp.async.commit_group;");
}
__device__ __forceinline__ void cp_wait1() {
    asm volatile("cp.async.wait_group 1;");
}
__device__ __forceinline__ void ffma2(uint64_t& acc, uint64_t a, uint64_t b) {
    asm("fma.rn.f32x2 %0, %1, %2, %0;" : "+l"(acc) : "l"(a), "l"(b));
}
__device__ __forceinline__ uint64_t pack2(float lo, float hi) {
    uint64_t r;
    asm("mov.b64 %0, {%1, %2};" : "=l"(r) : "f"(lo), "f"(hi));
    return r;
}
__device__ __forceinline__ float2 up2(uint64_t v) {
    float2 f; *(uint64_t*)&f = v; return f;
}

// Pair-packed weights: Wp[rp][m] = { W[n0][m], W[n0+4][m] }, n0 = nbase + 8*rp.
__device__ __forceinline__ void load_wp(const float* __restrict__ Wrowbase,
                                        uint64_t Wp[2][32]) {
    #pragma unroll
    for (int rp = 0; rp < 2; rp++) {
        float ra[32], rb[32];
        const float4* pa = (const float4*)(Wrowbase + (8 * rp) * 32);
        const float4* pb = (const float4*)(Wrowbase + (8 * rp + 4) * 32);
        #pragma unroll
        for (int g = 0; g < 8; g++) {
            float4 a = pa[g], b = pb[g];
            ra[4*g] = a.x; ra[4*g+1] = a.y; ra[4*g+2] = a.z; ra[4*g+3] = a.w;
            rb[4*g] = b.x; rb[4*g+1] = b.y; rb[4*g+2] = b.z; rb[4*g+3] = b.w;
        }
        #pragma unroll
        for (int m = 0; m < 32; m++) Wp[rp][m] = pack2(ra[m], rb[m]);
    }
}

// Diagonal core: xv = {x_t0, x_t1}.
//   accD[rp] += Wp[rp]*{x0,x1} = { w_n0*x0, w_n1*x1 }
//   accS[rp] += Wp[rp]*{x1,x0} = { w_n0*x1, w_n1*x0 }
__device__ __forceinline__ void core_m(const uint64_t Wp[2][32], int m,
                                       uint64_t xv,
                                       uint64_t accD[2], uint64_t accS[2]) {
    float2 f = up2(xv);
    uint64_t sw = pack2(f.y, f.x);
    ffma2(accD[0], Wp[0][m], xv);
    ffma2(accS[0], Wp[0][m], sw);
    ffma2(accD[1], Wp[1][m], xv);
    ffma2(accS[1], Wp[1][m], sw);
}

__global__ __launch_bounds__(256, 2)
void monarch_stage1(const float* __restrict__ x, const float* __restrict__ L,
                    int ntiles) {
    extern __shared__ float sm[];        // buf0|buf1 : xs[bl][m][slot]
    const int tid  = threadIdx.x;
    const int warp = tid >> 5;           // (bl = warp&3, g = warp>>2)
    const int lane = tid & 31;
    const int bl = warp & 3, g = warp >> 2;
    const int nh = lane & 3, th = lane >> 2;    // th in [0,8): t = 2th, 2th+1
    const int s  = blockIdx.x & 7;
    const int b  = 4 * s + bl;

    uint64_t Wp[2][32];                  // rows n = 16g + 8rp + {0,4} + nh
    load_wp(L + b * 1024 + (16 * g + nh) * 32, Wp);

    const unsigned sbase = smem_addr(sm);
    const int tstep = gridDim.x >> 3;
    const int tile0 = blockIdx.x >> 3;

    // Fill roles: warp -> (fm = (warp&3)*8, ftp = warp>>2);
    // lane -> (fcm = lane&7 -> m = fm+fcm, ftk = lane>>3).
    // Thread covers t = ftp*8 + ftk*2 + {0,1}, all 4 bl via float4.
    const int fm  = (warp & 3) * 8 + (lane & 7);
    const int ftb = (warp >> 2) * 8 + (lane >> 3) * 2;   // t of pf[0]
    const int fmx = fm & 3;

    // Prefetch tile0.
    float4 pf0, pf1;
    if (tile0 < ntiles) {
        const float* src = x + (tile0 * TILE_T + ftb) * 1024 + fm * 32 + 4 * s;
        pf0 = *(const float4*)(src);
        pf1 = *(const float4*)(src + 1024);
    }

    int cur = 0;
    for (int tile = tile0; tile < ntiles; tile += tstep) {
        // STS prefetched data into buf[cur] (swizzled quad slots).
        {
            unsigned dst = sbase + (cur * XS_FLOATS + fm * 16) * 4;
            const float v0[4] = {pf0.x, pf0.y, pf0.z, pf0.w};
            const float v1[4] = {pf1.x, pf1.y, pf1.z, pf1.w};
            #pragma unroll
            for (int o = 0; o < 2; o++) {
                int t = ftb + o;
                int off = ((((t >> 2) ^ fmx) & 3) << 2) | (t & 3);
                const float* v = o ? v1 : v0;
                #pragma unroll
                for (int e = 0; e < 4; e++) {
                    asm volatile("st.shared.f32 [%0], %1;"
                                 :: "r"(dst + (e * BROW + off) * 4), "f"(v[e]));
                }
            }
        }
        __syncthreads();                 // buf[cur] complete; prev reads done

        // Prefetch next tile (latency overlaps compute).
        int nxt = tile + tstep;
        if (nxt < ntiles) {
            const float* src = x + (nxt * TILE_T + ftb) * 1024 + fm * 32 + 4 * s;
            pf0 = *(const float4*)(src);
            pf1 = *(const float4*)(src + 1024);
        }

        uint64_t accD[2] = {0, 0}, accS[2] = {0, 0};
        const float* xw = sm + cur * XS_FLOATS + bl * BROW;
        #pragma unroll
        for (int m = 0; m < 32; m++) {
            // slot: quad = (th>>1) ^ (m&3), offset (th&1)*2 -> t = 2th + {0,1}
            uint64_t xv = *(const uint64_t*)(xw + m * 16
                           + ((((th >> 1) ^ m) & 3) << 2) + ((th & 1) << 1));
            core_m(Wp, m, xv, accD, accS);
        }

        // Epilogue: rows n0 = 16g+8rp+nh (t-pair {D.lo, S.lo}),
        //           n1 = n0+4          (t-pair {S.hi, D.hi}). STG.64 each.
        float* gp = g_h2 + tile * 16384 + b * 512 + 2 * th;
        #pragma unroll
        for (int rp = 0; rp < 2; rp++) {
            float2 D = up2(accD[rp]), S = up2(accS[rp]);
            *(uint64_t*)(gp + (16 * g + 8 * rp + nh) * 16) = pack2(D.x, S.x);
            *(uint64_t*)(gp + (16 * g + 8 * rp + 4 + nh) * 16) = pack2(S.y, D.y);
        }

        cur ^= 1;
    }
}

__global__ __launch_bounds__(256, 2)
void monarch_stage2(const float* __restrict__ R, float* __restrict__ out,
                    int ntiles) {
    extern __shared__ float sm[];        // buf0|buf1 : hs[jl][m][slot] ; then os
    float* os = sm + 2 * XS_FLOATS;      // os[i][jl][t] : i*72 + jl*18 + t
    const int tid  = threadIdx.x;
    const int warp = tid >> 5;
    const int lane = tid & 31;
    const int jl = warp & 3, g = warp >> 2;
    const int ih = lane & 3, th = lane >> 2;
    const int s  = blockIdx.x & 7;
    const int j  = 4 * s + jl;

    uint64_t Wp[2][32];                  // rows i = 16g + 8rp + {0,4} + ih
    load_wp(R + j * 1024 + (16 * g + ih) * 32, Wp);

    const unsigned sbase = smem_addr(sm);
    const int tstep = gridDim.x >> 3;
    const int tile0 = blockIdx.x >> 3;

    // Fill: 2 cp.async16/thread. idx = tid + 256k: ctq = idx&3,
    // cjl = (idx>>2)&3, cm = idx>>4. slot quad = ctq ^ cjl.
    if (tile0 < ntiles) {
        #pragma unroll
        for (int k = 0; k < 2; k++) {
            int idx = tid + 256 * k;
            int ctq = idx & 3, cjl = (idx >> 2) & 3, cm = idx >> 4;
            const float* src = g_h2 + tile0 * 16384 + cm * 512 + (4 * s + cjl) * 16 + ctq * 4;
            cp_async16(sbase + (cjl * BROW + cm * 16 + ((ctq ^ cjl) << 2)) * 4, src);
        }
    }
    cp_commit();

    int cur = 0;
    for (int tile = tile0; tile < ntiles; tile += tstep) {
        int nxt = tile + tstep;
        if (nxt < ntiles) {
            #pragma unroll
            for (int k = 0; k < 2; k++) {
                int idx = tid + 256 * k;
                int ctq = idx & 3, cjl = (idx >> 2) & 3, cm = idx >> 4;
                const float* src = g_h2 + nxt * 16384 + cm * 512 + (4 * s + cjl) * 16 + ctq * 4;
                cp_async16(sbase + ((cur ^ 1) * XS_FLOATS
                           + cjl * BROW + cm * 16 + ((ctq ^ cjl) << 2)) * 4, src);
            }
        }
        cp_commit();
        cp_wait1();
        __syncthreads();                 // hs[cur] ready; prev flush reads done

        uint64_t accD[2] = {0, 0}, accS[2] = {0, 0};
        const float* hw = sm + cur * XS_FLOATS + jl * BROW;
        #pragma unroll
        for (int m = 0; m < 32; m++) {
            uint64_t hv = *(const uint64_t*)(hw + m * 16
                           + ((((th >> 1) ^ jl) & 3) << 2) + ((th & 1) << 1));
            core_m(Wp, m, hv, accD, accS);
        }

        // Stage to os[i][jl][t]: STS.64 per row (banks 8*ih + 2*th: all distinct).
        #pragma unroll
        for (int rp = 0; rp < 2; rp++) {
            float2 D = up2(accD[rp]), S = up2(accS[rp]);
            *(uint64_t*)(os + (16 * g + 8 * rp + ih) * 72 + jl * 18 + 2 * th)
                = pack2(D.x, S.x);
            *(uint64_t*)(os + (16 * g + 8 * rp + 4 + ih) * 72 + jl * 18 + 2 * th)
                = pack2(S.y, D.y);
        }
        __syncthreads();

        // Flush: out[t][i*32 + 4s + jl] = os[i][jl][t].
        const int t0 = tile * TILE_T;
        #pragma unroll
        for (int k = 0; k < 8; k++) {
            int e = tid + 256 * k;       // e in [0,2048)
            int fjl = e & 3, fi = (e >> 2) & 31, t = e >> 7;
            out[(t0 + t) * 1024 + fi * 32 + 4 * s + fjl] = os[fi * 72 + fjl * 18 + t];
        }
        // os/hs reuse fenced by loop-top __syncthreads.
        cur ^= 1;
    }
}

extern "C" void kernel_launch(void* const* d_in, const int* in_sizes, int n_in,
                              void* d_out, int out_size) {
    const float* x = (const float*)d_in[0];
    const float* L = (const float*)d_in[1];
    const float* R = (const float*)d_in[2];
    float* out = (float*)d_out;

    const int ntok   = in_sizes[0] / 1024;   // 32768
    const int ntiles = ntok / TILE_T;        // 2048

    cudaFuncSetAttribute(monarch_stage1,
                         cudaFuncAttributeMaxDynamicSharedMemorySize, SMEM1_BYTES);
    cudaFuncSetAttribute(monarch_stage2,
                         cudaFuncAttributeMaxDynamicSharedMemorySize, SMEM2_BYTES);

    int sms = 148;
    cudaDeviceGetAttribute(&sms, cudaDevAttrMultiProcessorCount, 0);
    int grid = 8 * ((2 * sms) / 8);          // 296: 8 eighths x 37 tile-chains

    monarch_stage1<<<grid, 256, SMEM1_BYTES>>>(x, L, ntiles);
    monarch_stage2<<<grid, 256, SMEM2_BYTES>>>(R, out, ntiles);
}

// round 15
// speedup vs baseline: 1.2848x; 1.2848x over previous
#include <cuda_runtime.h>
#include <cstdint>

// MonarchOutProjection:
//   h2[t][b][n]    = sum_m L[b][n][m] * x[t][m*32+b]
//   out[t][i*32+j] = sum_m R[j][i][m] * h2[t][m][j]
//
// R13 = R9 structure with within-warp split-K: lane = (nh in [0,16), mh in
// {0,1}); thread computes partials for rows {nh, nh+16} over m in
// [16mh, 16mh+16), all 16 t; partials combined by shfl.xor(16) + f32x2 add.
// 32 weight regs + 32 acc regs -> ~80 regs -> 3 CTAs/SM (24 warps, +50%).
// Crossbar bytes unchanged from R9. Quad slots XOR'd by mh (and jl in
// stage2) keep every LDS/STS bank-conflict-free.

#define TILE_T 16
#define BROW 516                        // per-block smem row: 32m*16t + 4
#define XS_FLOATS (8 * BROW)            // 4128 per buffer (8 blocks = quarter)
#define OS_FLOATS 4608                  // os[t][i][jl]: t*288 + i*9 + jl
#define SMEM1_BYTES (2 * XS_FLOATS * 4)                 // 33024
#define SMEM2_BYTES ((2 * XS_FLOATS + OS_FLOATS) * 4)   // 51456

// g_h2[tile][b][n][t] : idx = tile*16384 + b*512 + n*16 + t
__device__ float g_h2[33554432];

__device__ __forceinline__ unsigned smem_addr(const void* p) {
    return (unsigned)__cvta_generic_to_shared(p);
}
__device__ __forceinline__ void cp_async4(unsigned dst, const float* src) {
    asm volatile("cp.async.ca.shared.global [%0], [%1], 4;" :: "r"(dst), "l"(src));
}
__device__ __forceinline__ void cp_async16(unsigned dst, const float* src) {
    asm volatile("cp.async.cg.shared.global [%0], [%1], 16;" :: "r"(dst), "l"(src));
}
__device__ __forceinline__ void cp_commit() {
    asm volatile("cp.async.commit_group;");
}
__device__ __forceinline__ void cp_wait1() {
    asm volatile("cp.async.wait_group 1;");
}
__device__ __forceinline__ void ffma2(uint64_t& acc, uint64_t a, uint64_t b) {
    asm("fma.rn.f32x2 %0, %1, %2, %0;" : "+l"(acc) : "l"(a), "l"(b));
}
__device__ __forceinline__ void addf2(uint64_t& acc, uint64_t v) {
    asm("add.rn.f32x2 %0, %0, %1;" : "+l"(acc) : "l"(v));
}
__device__ __forceinline__ uint64_t splat2(float w) {
    uint64_t r;
    asm("mov.b64 %0, {%1, %1};" : "=l"(r) : "f"(w));
    return r;
}

// Load 16 weights W[row][16*mh + mm], mm = 0..15, as 4 float4.
__device__ __forceinline__ void load_w16(const float* __restrict__ p, float* w) {
    const float4* q = (const float4*)p;
    #pragma unroll
    for (int g = 0; g < 4; g++) {
        float4 v = q[g];
        w[4*g+0] = v.x; w[4*g+1] = v.y; w[4*g+2] = v.z; w[4*g+3] = v.w;
    }
}

__global__ __launch_bounds__(256, 3)
void monarch_stage1(const float* __restrict__ x, const float* __restrict__ L,
                    int ntiles) {
    extern __shared__ float sm[];        // buf0|buf1 : xs[bl][m][slot]
    const int tid  = threadIdx.x;
    const int warp = tid >> 5;           // bl in [0,8)
    const int lane = tid & 31;
    const int nh = lane & 15, mh = lane >> 4;   // split-K half
    const int q  = blockIdx.x & 3;       // quarter: blocks [8q, 8q+8)
    const int b  = 8 * q + warp;

    // Weights: Wr[r][mm] = L[b][nh+16r][16*mh + mm]  (32 regs)
    float Wr[2][16];
    load_w16(L + b * 1024 + nh * 32 + 16 * mh, Wr[0]);
    load_w16(L + b * 1024 + (nh + 16) * 32 + 16 * mh, Wr[1]);

    const unsigned sbase = smem_addr(sm);
    const int tstep = gridDim.x >> 2;
    const int tile0 = blockIdx.x >> 2;

    // Fill: thread = (cbl = tid&7, cm = tid>>3), 16 t, 4B each.
    // Slot quad XOR'd by (cm>>4) to match the compute-side mh swizzle.
    const int cbl = tid & 7, cm = tid >> 3;
    const int ck  = (cm >> 4) & 1;

    if (tile0 < ntiles) {
        const float* src = x + (tile0 * TILE_T) * 1024 + cm * 32 + 8 * q + cbl;
        unsigned dst = sbase + (cbl * BROW + cm * 16) * 4;
        #pragma unroll
        for (int t = 0; t < 16; t++) {
            int slot = (t & 3) | ((((t >> 2) ^ ck) & 3) << 2);
            cp_async4(dst + slot * 4, src + t * 1024);
        }
    }
    cp_commit();

    int cur = 0;
    for (int tile = tile0; tile < ntiles; tile += tstep) {
        int nxt = tile + tstep;
        if (nxt < ntiles) {
            const float* src = x + (nxt * TILE_T) * 1024 + cm * 32 + 8 * q + cbl;
            unsigned dst = sbase + ((cur ^ 1) * XS_FLOATS + cbl * BROW + cm * 16) * 4;
            #pragma unroll
            for (int t = 0; t < 16; t++) {
                int slot = (t & 3) | ((((t >> 2) ^ ck) & 3) << 2);
                cp_async4(dst + slot * 4, src + t * 1024);
            }
        }
        cp_commit();
        cp_wait1();
        __syncthreads();

        // Partials: acc[r][k] = rows nh+16r, t = {2k, 2k+1}, m in this half.
        uint64_t acc[2][8];
        #pragma unroll
        for (int r = 0; r < 2; r++)
            #pragma unroll
            for (int k = 0; k < 8; k++) acc[r][k] = 0ull;

        const float* xw = sm + cur * XS_FLOATS + warp * BROW;
        #pragma unroll
        for (int mm = 0; mm < 16; mm++) {
            const int m = 16 * mh + mm;
            const float* xr = xw + m * 16;
            uint64_t w0 = splat2(Wr[0][mm]);
            uint64_t w1 = splat2(Wr[1][mm]);
            #pragma unroll
            for (int qd = 0; qd < 4; qd++) {
                // quad slot = qd ^ mh (disjoint banks across the mh halves)
                ulonglong2 xv = *(const ulonglong2*)(xr + ((qd ^ mh) << 2));
                ffma2(acc[0][2*qd+0], w0, xv.x);
                ffma2(acc[0][2*qd+1], w0, xv.y);
                ffma2(acc[1][2*qd+0], w1, xv.x);
                ffma2(acc[1][2*qd+1], w1, xv.y);
            }
        }

        // Split-K reduce: keep t in [8mh, 8mh+8) (= acc idx 4mh..4mh+4),
        // exchange the other half with partner lane^16.
        uint64_t keep[2][4];
        #pragma unroll
        for (int r = 0; r < 2; r++)
            #pragma unroll
            for (int k = 0; k < 4; k++) {
                uint64_t snd = mh ? acc[r][k] : acc[r][k + 4];
                uint64_t rcv = __shfl_xor_sync(0xffffffffu,
                                               (unsigned long long)snd, 16);
                uint64_t kp  = mh ? acc[r][k + 4] : acc[r][k];
                addf2(kp, rcv);
                keep[r][k] = kp;
            }

        // Store: g_h2[tile][b][n][t], t-run [8mh, 8mh+8). STG.128 x2 per row.
        float* gp = g_h2 + tile * 16384 + b * 512 + mh * 8;
        #pragma unroll
        for (int r = 0; r < 2; r++) {
            float* rp = gp + (nh + 16 * r) * 16;
            ulonglong2 v0; v0.x = keep[r][0]; v0.y = keep[r][1];
            ulonglong2 v1; v1.x = keep[r][2]; v1.y = keep[r][3];
            *(ulonglong2*)(rp)     = v0;
            *(ulonglong2*)(rp + 4) = v1;
        }

        __syncthreads();   // fence buf[cur] reads before next refill (R8 lesson)
        cur ^= 1;
    }
}

__global__ __launch_bounds__(256, 3)
void monarch_stage2(const float* __restrict__ R, float* __restrict__ out,
                    int ntiles) {
    extern __shared__ float sm[];        // buf0|buf1 : hs[jl][m][slot] ; then os
    float* os = sm + 2 * XS_FLOATS;      // os[t][i][jl] : t*288 + i*9 + jl
    const int tid  = threadIdx.x;
    const int warp = tid >> 5;           // jl in [0,8)
    const int lane = tid & 31;
    const int nh = lane & 15, mh = lane >> 4;
    const int q  = blockIdx.x & 3;       // quarter: j in [8q, 8q+8)
    const int j  = 8 * q + warp;
    const int ws = warp & 3;             // per-warp quad XOR key

    float Wr[2][16];                     // R[j][nh+16r][16mh + mm]
    load_w16(R + j * 1024 + nh * 32 + 16 * mh, Wr[0]);
    load_w16(R + j * 1024 + (nh + 16) * 32 + 16 * mh, Wr[1]);

    const unsigned sbase = smem_addr(sm);
    const int tstep = gridDim.x >> 2;
    const int tile0 = blockIdx.x >> 2;

    // Fill: e = tid + 256k (k<4): ctq = e&3, cjl = (e>>2)&7, cm = e>>5.
    // hs[cjl][cm][slot] = g_h2[tile][cm][8q+cjl][4ctq..4ctq+4],
    // slot quad = ctq ^ (cjl&3) ^ (cm>>4).
    const int ctq = tid & 3, cjl = (tid >> 2) & 7, cmb = tid >> 5;

    if (tile0 < ntiles) {
        #pragma unroll
        for (int k = 0; k < 4; k++) {
            int m = cmb + k * 8;
            int slot = (ctq ^ (cjl & 3) ^ ((m >> 4) & 1)) & 3;
            const float* src = g_h2 + tile0 * 16384 + m * 512 + (8 * q + cjl) * 16 + ctq * 4;
            cp_async16(sbase + (cjl * BROW + m * 16 + (slot << 2)) * 4, src);
        }
    }
    cp_commit();

    int cur = 0;
    for (int tile = tile0; tile < ntiles; tile += tstep) {
        int nxt = tile + tstep;
        if (nxt < ntiles) {
            #pragma unroll
            for (int k = 0; k < 4; k++) {
                int m = cmb + k * 8;
                int slot = (ctq ^ (cjl & 3) ^ ((m >> 4) & 1)) & 3;
                const float* src = g_h2 + nxt * 16384 + m * 512 + (8 * q + cjl) * 16 + ctq * 4;
                cp_async16(sbase + ((cur ^ 1) * XS_FLOATS
                           + cjl * BROW + m * 16 + (slot << 2)) * 4, src);
            }
        }
        cp_commit();
        cp_wait1();
        __syncthreads();                 // hs[cur] ready; prev flush reads done

        uint64_t acc[2][8];
        #pragma unroll
        for (int r = 0; r < 2; r++)
            #pragma unroll
            for (int k = 0; k < 8; k++) acc[r][k] = 0ull;

        const float* hw = sm + cur * XS_FLOATS + warp * BROW;
        #pragma unroll
        for (int mm = 0; mm < 16; mm++) {
            const int m = 16 * mh + mm;
            const float* hr = hw + m * 16;
            uint64_t w0 = splat2(Wr[0][mm]);
            uint64_t w1 = splat2(Wr[1][mm]);
            #pragma unroll
            for (int qd = 0; qd < 4; qd++) {
                ulonglong2 hv = *(const ulonglong2*)(hr + (((qd ^ ws ^ mh) & 3) << 2));
                ffma2(acc[0][2*qd+0], w0, hv.x);
                ffma2(acc[0][2*qd+1], w0, hv.y);
                ffma2(acc[1][2*qd+0], w1, hv.x);
                ffma2(acc[1][2*qd+1], w1, hv.y);
            }
        }

        // Split-K reduce with partner lane^16.
        uint64_t keep[2][4];
        #pragma unroll
        for (int r = 0; r < 2; r++)
            #pragma unroll
            for (int k = 0; k < 4; k++) {
                uint64_t snd = mh ? acc[r][k] : acc[r][k + 4];
                uint64_t rcv = __shfl_xor_sync(0xffffffffu,
                                               (unsigned long long)snd, 16);
                uint64_t kp  = mh ? acc[r][k + 4] : acc[r][k];
                addf2(kp, rcv);
                keep[r][k] = kp;
            }

        // Stage to os[t][i][jl], t in [8mh, 8mh+8).
        #pragma unroll
        for (int r = 0; r < 2; r++) {
            float* op = os + (nh + 16 * r) * 9 + warp;
            #pragma unroll
            for (int p = 0; p < 4; p++) {
                float2 pr; *(uint64_t*)&pr = keep[r][p];
                op[(8 * mh + 2 * p + 0) * 288] = pr.x;
                op[(8 * mh + 2 * p + 1) * 288] = pr.y;
            }
        }
        __syncthreads();

        // Coalesced flush: out[t][i*32 + 8q + jl].
        const int t0 = tile * TILE_T;
        #pragma unroll
        for (int k = 0; k < 16; k++) {
            int e = tid + k * 256;
            int jl = e & 7, i2 = (e >> 3) & 31, t = e >> 8;
            out[(t0 + t) * 1024 + i2 * 32 + 8 * q + jl] = os[t * 288 + i2 * 9 + jl];
        }
        // os/hs reuse fenced by loop-top __syncthreads.
        cur ^= 1;
    }
}

extern "C" void kernel_launch(void* const* d_in, const int* in_sizes, int n_in,
                              void* d_out, int out_size) {
    const float* x = (const float*)d_in[0];
    const float* L = (const float*)d_in[1];
    const float* R = (const float*)d_in[2];
    float* out = (float*)d_out;

    const int ntok   = in_sizes[0] / 1024;   // 32768
    const int ntiles = ntok / TILE_T;        // 2048

    cudaFuncSetAttribute(monarch_stage1,
                         cudaFuncAttributeMaxDynamicSharedMemorySize, SMEM1_BYTES);
    cudaFuncSetAttribute(monarch_stage2,
                         cudaFuncAttributeMaxDynamicSharedMemorySize, SMEM2_BYTES);

    int sms = 148;
    cudaDeviceGetAttribute(&sms, cudaDevAttrMultiProcessorCount, 0);
    int grid = 4 * ((3 * sms) / 4);          // 4 quarters, 3 CTAs/SM

    monarch_stage1<<<grid, 256, SMEM1_BYTES>>>(x, L, ntiles);
    monarch_stage2<<<grid, 256, SMEM2_BYTES>>>(R, out, ntiles);
}

// round 17
// speedup vs baseline: 1.5514x; 1.2075x over previous
#include <cuda_runtime.h>
#include <cstdint>

// MonarchOutProjection:
//   h2[t][b][n]    = sum_m L[b][n][m] * x[t][m*32+b]
//   out[t][i*32+j] = sum_m R[j][i][m] * h2[t][m][j]
//
// R15 = R9 (champion) with weights moved from 64 regs/thread to pre-splatted
// u64 lines in global scratch, read by uniform LDG.64 per (m, row-half).
// Same instruction count per warp-m (20); regs ~125 -> ~50 -> 4 CTAs/SM
// (32 warps, 2x R9's latency hiding). Everything else byte-identical to R9.

#define TILE_T 16
#define BROW 516                        // per-block smem row: 32m*16t + 4
#define XS_FLOATS (8 * BROW)            // 4128 per buffer (8 blocks = quarter)
#define OS_FLOATS 4608                  // os[t][i][jl]: t*288 + i*9 + jl
#define SMEM1_BYTES (2 * XS_FLOATS * 4)                 // 33024
#define SMEM2_BYTES ((2 * XS_FLOATS + OS_FLOATS) * 4)   // 51456

// g_h2[tile][b][n][t] : idx = tile*16384 + b*512 + n*16 + t
__device__ float g_h2[33554432];

// Pre-splatted weights: g_Ws[b][m][r][nh] = {w, w} with w = W[b][nh+16r][m].
// One (b, m, r) row = 16 u64 = 128B line, read by one uniform LDG.64/warp.
__device__ uint64_t g_Ws1[32768];       // from L
__device__ uint64_t g_Ws2[32768];       // from R

__device__ __forceinline__ unsigned smem_addr(const void* p) {
    return (unsigned)__cvta_generic_to_shared(p);
}
__device__ __forceinline__ void cp_async4(unsigned dst, const float* src) {
    asm volatile("cp.async.ca.shared.global [%0], [%1], 4;" :: "r"(dst), "l"(src));
}
__device__ __forceinline__ void cp_async16(unsigned dst, const float* src) {
    asm volatile("cp.async.cg.shared.global [%0], [%1], 16;" :: "r"(dst), "l"(src));
}
__device__ __forceinline__ void cp_commit() {
    asm volatile("cp.async.commit_group;");
}
__device__ __forceinline__ void cp_wait1() {
    asm volatile("cp.async.wait_group 1;");
}
__device__ __forceinline__ void ffma2(uint64_t& acc, uint64_t a, uint64_t b) {
    asm("fma.rn.f32x2 %0, %1, %2, %0;" : "+l"(acc) : "l"(a), "l"(b));
}
__device__ __forceinline__ uint64_t ldg64(const uint64_t* p) {
    uint64_t v;
    asm("ld.global.nc.b64 %0, [%1];" : "=l"(v) : "l"(p));
    return v;
}

// Prep: pack W[b][nh+16r][m] splatted into dst[((b*32+m)*2+r)*16+nh].
__global__ void pack_weights(const float* __restrict__ W,
                             uint64_t* __restrict__ dst) {
    int idx = blockIdx.x * 256 + threadIdx.x;     // 32768 total
    int b = idx >> 10, m = (idx >> 5) & 31, r = (idx >> 4) & 1, nh = idx & 15;
    float w = W[b * 1024 + (nh + 16 * r) * 32 + m];
    uint64_t v;
    asm("mov.b64 %0, {%1, %1};" : "=l"(v) : "f"(w));
    dst[idx] = v;   // idx == ((b*32+m)*2+r)*16+nh by construction
}

__global__ __launch_bounds__(256, 4)
void monarch_stage1(const float* __restrict__ x, int ntiles) {
    extern __shared__ float sm[];        // buf0|buf1 : xs[bl][m][t-slot]
    const int tid  = threadIdx.x;
    const int warp = tid >> 5;           // bl in [0,8)
    const int lane = tid & 31;
    const int nh = lane & 15, th = lane >> 4;
    const int q  = blockIdx.x & 3;       // quarter: blocks [8q, 8q+8)
    const int b  = 8 * q + warp;

    // Weight line base: g_Ws1 + ((b*32 + m)*2 + r)*16 + nh
    const uint64_t* wbase = g_Ws1 + (b * 64) * 16 + nh;

    const unsigned sbase = smem_addr(sm);
    const int tstep = gridDim.x >> 2;
    const int tile0 = blockIdx.x >> 2;

    // Fill mapping: thread = (cbl = tid&7, cm = tid>>3), 16 t-values, 4B each.
    const int cbl = tid & 7, cm = tid >> 3;
    const int cmx = cm & 3;

    if (tile0 < ntiles) {
        const float* src = x + (tile0 * TILE_T) * 1024 + cm * 32 + 8 * q + cbl;
        unsigned dst = sbase + (cbl * BROW + cm * 16) * 4;
        #pragma unroll
        for (int t = 0; t < 16; t++) {
            int slot = (t & 3) | ((((t >> 2) ^ cmx) & 3) << 2);
            cp_async4(dst + slot * 4, src + t * 1024);
        }
    }
    cp_commit();

    int cur = 0;
    for (int tile = tile0; tile < ntiles; tile += tstep) {
        int nxt = tile + tstep;
        if (nxt < ntiles) {
            const float* src = x + (nxt * TILE_T) * 1024 + cm * 32 + 8 * q + cbl;
            unsigned dst = sbase + ((cur ^ 1) * XS_FLOATS + cbl * BROW + cm * 16) * 4;
            #pragma unroll
            for (int t = 0; t < 16; t++) {
                int slot = (t & 3) | ((((t >> 2) ^ cmx) & 3) << 2);
                cp_async4(dst + slot * 4, src + t * 1024);
            }
        }
        cp_commit();
        cp_wait1();
        __syncthreads();

        // acc[r][p] covers n = nh+16r, t = 8*th + 2p, 2p+1
        uint64_t acc[2][4];
        #pragma unroll
        for (int r = 0; r < 2; r++)
            #pragma unroll
            for (int p = 0; p < 4; p++) acc[r][p] = 0ull;

        const float* xw = sm + cur * XS_FLOATS + warp * BROW;
        #pragma unroll
        for (int m = 0; m < 32; m++) {
            const ulonglong2* xq = (const ulonglong2*)(xw + m * 16);
            ulonglong2 xv0 = xq[(2 * th)     ^ (m & 3)];
            ulonglong2 xv1 = xq[(2 * th + 1) ^ (m & 3)];
            uint64_t w0 = ldg64(wbase + (m * 2 + 0) * 16);   // uniform 128B line
            uint64_t w1 = ldg64(wbase + (m * 2 + 1) * 16);
            ffma2(acc[0][0], w0, xv0.x); ffma2(acc[0][1], w0, xv0.y);
            ffma2(acc[0][2], w0, xv1.x); ffma2(acc[0][3], w0, xv1.y);
            ffma2(acc[1][0], w1, xv0.x); ffma2(acc[1][1], w1, xv0.y);
            ffma2(acc[1][2], w1, xv1.x); ffma2(acc[1][3], w1, xv1.y);
        }

        // Store: g_h2[tile][b][n][t].
        float* gp = g_h2 + tile * 16384 + b * 512 + th * 8;
        #pragma unroll
        for (int r = 0; r < 2; r++) {
            float* rp = gp + (nh + 16 * r) * 16;
            ulonglong2 v0; v0.x = acc[r][0]; v0.y = acc[r][1];
            ulonglong2 v1; v1.x = acc[r][2]; v1.y = acc[r][3];
            *(ulonglong2*)(rp)     = v0;
            *(ulonglong2*)(rp + 4) = v1;
        }

        // Fence buf[cur] reads before the next iteration's cp.async refill.
        __syncthreads();

        cur ^= 1;
    }
}

__global__ __launch_bounds__(256, 4)
void monarch_stage2(float* __restrict__ out, int ntiles) {
    extern __shared__ float sm[];        // buf0|buf1 : hs[jl][m][t-slot] ; then os
    float* os = sm + 2 * XS_FLOATS;      // os[t][i][jl] : t*288 + i*9 + jl
    const int tid  = threadIdx.x;
    const int warp = tid >> 5;           // jl in [0,8)
    const int lane = tid & 31;
    const int nh = lane & 15, th = lane >> 4;
    const int q  = blockIdx.x & 3;       // quarter: j in [8q, 8q+8)
    const int j  = 8 * q + warp;
    const int ws = warp & 3;             // per-warp quad XOR key

    const uint64_t* wbase = g_Ws2 + (j * 64) * 16 + nh;

    const unsigned sbase = smem_addr(sm);
    const int tstep = gridDim.x >> 2;
    const int tile0 = blockIdx.x >> 2;

    // Fill: e = tid + 256k (k<4): ctq = e&3, cjl = (e>>2)&7, cm = e>>5.
    const int ctq = tid & 3, cjl = (tid >> 2) & 7, cmb = tid >> 5;

    if (tile0 < ntiles) {
        #pragma unroll
        for (int k = 0; k < 4; k++) {
            int m = cmb + k * 8;
            const float* src = g_h2 + tile0 * 16384 + m * 512 + (8 * q + cjl) * 16 + ctq * 4;
            unsigned dst = sbase + (cjl * BROW + m * 16 + ((ctq ^ (cjl & 3)) << 2)) * 4;
            cp_async16(dst, src);
        }
    }
    cp_commit();

    int cur = 0;
    for (int tile = tile0; tile < ntiles; tile += tstep) {
        int nxt = tile + tstep;
        if (nxt < ntiles) {
            #pragma unroll
            for (int k = 0; k < 4; k++) {
                int m = cmb + k * 8;
                const float* src = g_h2 + nxt * 16384 + m * 512 + (8 * q + cjl) * 16 + ctq * 4;
                unsigned dst = sbase + ((cur ^ 1) * XS_FLOATS
                               + cjl * BROW + m * 16 + ((ctq ^ (cjl & 3)) << 2)) * 4;
                cp_async16(dst, src);
            }
        }
        cp_commit();
        cp_wait1();
        __syncthreads();                 // hs[cur] ready; prev flush reads done

        uint64_t acc[2][4];
        #pragma unroll
        for (int r = 0; r < 2; r++)
            #pragma unroll
            for (int p = 0; p < 4; p++) acc[r][p] = 0ull;

        const float* hw = sm + cur * XS_FLOATS + warp * BROW;
        #pragma unroll
        for (int m = 0; m < 32; m++) {
            const ulonglong2* hq = (const ulonglong2*)(hw + m * 16);
            ulonglong2 hv0 = hq[(2 * th)     ^ ws];
            ulonglong2 hv1 = hq[(2 * th + 1) ^ ws];
            uint64_t w0 = ldg64(wbase + (m * 2 + 0) * 16);
            uint64_t w1 = ldg64(wbase + (m * 2 + 1) * 16);
            ffma2(acc[0][0], w0, hv0.x); ffma2(acc[0][1], w0, hv0.y);
            ffma2(acc[0][2], w0, hv1.x); ffma2(acc[0][3], w0, hv1.y);
            ffma2(acc[1][0], w1, hv0.x); ffma2(acc[1][1], w1, hv0.y);
            ffma2(acc[1][2], w1, hv1.x); ffma2(acc[1][3], w1, hv1.y);
        }

        // Stage to os[t][i][jl]; barrier also fences hs[cur] reads.
        #pragma unroll
        for (int r = 0; r < 2; r++) {
            float* op = os + (nh + 16 * r) * 9 + warp;
            #pragma unroll
            for (int p = 0; p < 4; p++) {
                float2 pr; *(uint64_t*)&pr = acc[r][p];
                op[(8 * th + 2 * p + 0) * 288] = pr.x;
                op[(8 * th + 2 * p + 1) * 288] = pr.y;
            }
        }
        __syncthreads();

        // Coalesced flush: out[t][i*32 + 8q + jl].
        const int t0 = tile * TILE_T;
        #pragma unroll
        for (int k = 0; k < 16; k++) {
            int e = tid + k * 256;
            int jl = e & 7, i2 = (e >> 3) & 31, t = e >> 8;
            out[(t0 + t) * 1024 + i2 * 32 + 8 * q + jl] = os[t * 288 + i2 * 9 + jl];
        }
        cur ^= 1;
    }
}

extern "C" void kernel_launch(void* const* d_in, const int* in_sizes, int n_in,
                              void* d_out, int out_size) {
    const float* x = (const float*)d_in[0];
    const float* L = (const float*)d_in[1];
    const float* R = (const float*)d_in[2];
    float* out = (float*)d_out;

    const int ntok   = in_sizes[0] / 1024;   // 32768
    const int ntiles = ntok / TILE_T;        // 2048

    cudaFuncSetAttribute(monarch_stage1,
                         cudaFuncAttributeMaxDynamicSharedMemorySize, SMEM1_BYTES);
    cudaFuncSetAttribute(monarch_stage2,
                         cudaFuncAttributeMaxDynamicSharedMemorySize, SMEM2_BYTES);

    int sms = 148;
    cudaDeviceGetAttribute(&sms, cudaDevAttrMultiProcessorCount, 0);
    int grid = 4 * ((4 * sms) / 4);          // 4 quarters, 4 CTAs/SM

    // Pre-splat weights into u64 lines (one-time per launch, ~us).
    uint64_t* ws1; cudaGetSymbolAddress((void**)&ws1, g_Ws1);
    uint64_t* ws2; cudaGetSymbolAddress((void**)&ws2, g_Ws2);
    pack_weights<<<128, 256>>>(L, ws1);
    pack_weights<<<128, 256>>>(R, ws2);

    monarch_stage1<<<grid, 256, SMEM1_BYTES>>>(x, ntiles);
    monarch_stage2<<<grid, 256, SMEM2_BYTES>>>(out, ntiles);
}